// round 3
// baseline (speedup 1.0000x reference)
#include <cuda_runtime.h>
#include <math.h>

#define Lc 37
#define Kc 8
#define HMc 512
#define HSc 128
#define HCc 64
#define Bc 2
#define NIMG  (Bc*Lc*Kc)
#define NIMGP (Lc*Kc)
#define NBL   (Bc*Lc)
#define NH 129

// ---------------- device scratch ----------------
__device__ float  g_tmpA[NBL*HMc*HSc];        // r1 out [bl*512+y][128]; reused by u1 as [bl*128+y][512]
__device__ float  g_hmrs[NBL*HSc*HSc];
__device__ float  g_prior[NIMGP*HSc*HSc];
__device__ float2 g_RL[NIMG*HSc*NH];
__device__ float2 g_RP[NIMGP*HSc*NH];
__device__ float2 g_SP[NIMGP*NH*256];
__device__ float2 g_TL[NIMG*HSc*NH];
__device__ float  g_energy128[NBL*HSc*HSc];
__device__ float  g_energy512[NBL*HMc*HMc];
__device__ float2 g_bnp[Lc*32];
__device__ float  g_mean[Lc], g_scale[Lc];
__device__ float  g_rowmax[NBL*HMc];
__device__ float  g_maxv[NBL];
__device__ float4 g_part[NBL*HMc];
__device__ float2 g_twid[128];
__device__ float  g_wD[HSc][16];
__device__ float  g_wU64[HSc][4];
__device__ int    g_wU64s[HSc];
__device__ float  g_wU128[HMc][4];
__device__ int    g_wU128s[HMc];

__device__ __forceinline__ float2 cmul(float2 a, float2 b){
  return make_float2(a.x*b.x - a.y*b.y, a.x*b.y + a.y*b.x);
}
__device__ __forceinline__ float spb(float x){
  float t = 5.f*x;
  return 0.2f*(fmaxf(t,0.f) + log1pf(expf(-fabsf(t))));
}
__device__ double keysd(double x){
  if (x >= 2.0) return 0.0;
  if (x >= 1.0) return ((-0.5*x + 2.5)*x - 4.0)*x + 2.0;
  return ((1.5*x - 2.5)*x)*x + 1.0;
}

// 256-pt radix-2 FFT in smem; 128 threads (t) per line; all block threads call it.
__device__ __forceinline__ void fft256(float2* s, int t, bool inv){
  __syncthreads();
  {
    int i=t, j=__brev((unsigned)i)>>24;
    if (j>i){ float2 a=s[i]; s[i]=s[j]; s[j]=a; }
    i=t+128; j=__brev((unsigned)i)>>24;
    if (j>i){ float2 a=s[i]; s[i]=s[j]; s[j]=a; }
  }
  __syncthreads();
#pragma unroll
  for (int st=1; st<=8; st++){
    int half = 1<<(st-1);
    int p = t & (half-1);
    int i0 = ((t>>(st-1))<<st) + p;
    int i1 = i0 + half;
    float2 w = g_twid[p<<(8-st)];
    float wy = inv ? -w.y : w.y;
    float2 a=s[i0], b=s[i1];
    float2 wb = make_float2(w.x*b.x - wy*b.y, w.x*b.y + wy*b.x);
    s[i0] = make_float2(a.x+wb.x, a.y+wb.y);
    s[i1] = make_float2(a.x-wb.x, a.y-wb.y);
    __syncthreads();
  }
}

// ---------------- setup ----------------
__global__ void k_setup(){
  int t = threadIdx.x;
  if (t < 128){
    double sv,cv; sincospi(-(double)t/128.0, &sv, &cv);
    g_twid[t] = make_float2((float)cv,(float)sv);
  }
  if (t < HSc){
    double sf = 4.0*t + 1.5;
    int s0 = 4*t - 6;
    double w[16], ws=0.0;
    for (int j=0;j<16;j++){
      int i=s0+j;
      double kv = keysd(fabs(sf-(double)i)*0.25);
      if (i<0 || i>511) kv=0.0;
      w[j]=kv; ws+=kv;
    }
    for (int j=0;j<16;j++) g_wD[t][j]=(float)(w[j]/ws);
    double sf2 = 0.5*t - 0.25;
    int b0 = (int)floor(sf2)-1;
    g_wU64s[t]=b0;
    double w4[4]; ws=0.0;
    for (int j=0;j<4;j++){
      int i=b0+j;
      double kv = keysd(fabs(sf2-(double)i));
      if (i<0||i>63) kv=0.0;
      w4[j]=kv; ws+=kv;
    }
    for (int j=0;j<4;j++) g_wU64[t][j]=(float)(w4[j]/ws);
  }
  if (t < HMc){
    double sf = 0.25*t - 0.375;
    int b0 = (int)floor(sf)-1;
    g_wU128s[t]=b0;
    double w4[4], ws=0.0;
    for (int j=0;j<4;j++){
      int i=b0+j;
      double kv = keysd(fabs(sf-(double)i));
      if (i<0||i>127) kv=0.0;
      w4[j]=kv; ws+=kv;
    }
    for (int j=0;j<4;j++) g_wU128[t][j]=(float)(w4[j]/ws);
  }
}

// ---------------- batchnorm ----------------
__global__ void k_bn_partial(const float* __restrict__ heat){
  int l = blockIdx.x, nb = blockIdx.y;
  const float* p0 = heat + (size_t)l*262144;
  const float* p1 = heat + (size_t)(Lc+l)*262144;
  float s=0.f, ss=0.f;
  int end=(nb+1)*16384;
  for (int i=threadIdx.x+nb*16384; i<end; i+=256){
    float v = (i<262144)? p0[i] : p1[i-262144];
    s+=v; ss=fmaf(v,v,ss);
  }
  __shared__ float sa[256], sb[256];
  sa[threadIdx.x]=s; sb[threadIdx.x]=ss; __syncthreads();
  for (int o=128;o>0;o>>=1){
    if (threadIdx.x<o){ sa[threadIdx.x]+=sa[threadIdx.x+o]; sb[threadIdx.x]+=sb[threadIdx.x+o]; }
    __syncthreads();
  }
  if (!threadIdx.x) g_bnp[l*32+nb]=make_float2(sa[0],sb[0]);
}
__global__ void k_bn_final(const float* __restrict__ gamma){
  int t=threadIdx.x;
  if (t<Lc){
    float s=0.f, ss=0.f;
    for (int j=0;j<32;j++){ float2 v=g_bnp[t*32+j]; s+=v.x; ss+=v.y; }
    const float N=524288.f;
    float mean=s/N, var=ss/N-mean*mean;
    g_mean[t]=mean;
    g_scale[t]=gamma[t]*rsqrtf(var+1e-5f);
  }
}

// ---------------- resize 512->128 (BN folded) ----------------
__global__ void k_r1(const float* __restrict__ heat, const float* __restrict__ beta){
  int row = blockIdx.x;          // bl*512+y
  int bl = row>>9, l = bl % Lc;
  const float* src = heat + (size_t)row*HMc;
  float mean=g_mean[l], sc=g_scale[l], be=beta[l];
  int oc = threadIdx.x;
  int s0 = 4*oc-6;
  float acc=0.f;
#pragma unroll
  for (int j=0;j<16;j++){
    int i = min(max(s0+j,0),HMc-1);
    acc = fmaf(g_wD[oc][j], src[i], acc);
  }
  g_tmpA[(size_t)row*HSc+oc] = (acc-mean)*sc + be;
}
__global__ void k_r2(){
  int orow = blockIdx.x;         // bl*128+oy
  int bl = orow>>7, oy = orow&127;
  int oc = threadIdx.x;
  int s0 = 4*oy-6;
  float acc=0.f;
#pragma unroll
  for (int j=0;j<16;j++){
    int i = min(max(s0+j,0),HMc-1);
    acc = fmaf(g_wD[oy][j], g_tmpA[((size_t)bl*HMc+i)*HSc+oc], acc);
  }
  g_hmrs[(size_t)orow*HSc+oc] = acc;
}

// ---------------- prior ----------------
__global__ void k_prior(const float* __restrict__ cond){
  int orow = blockIdx.x;         // imgp*128+oy
  int imgp = orow>>7, oy = orow&127;
  int ox = threadIdx.x;
  int sy=g_wU64s[oy], sx=g_wU64s[ox];
  const float* src = cond + (size_t)imgp*HCc*HCc;
  float acc=0.f;
#pragma unroll
  for (int a=0;a<4;a++){
    int iy = min(max(sy+a,0),HCc-1);
    float r=0.f;
#pragma unroll
    for (int b2=0;b2<4;b2++){
      int ix = min(max(sx+b2,0),HCc-1);
      r = fmaf(g_wU64[ox][b2], src[iy*HCc+ix], r);
    }
    acc = fmaf(g_wU64[oy][a], r, acc);
  }
  g_prior[(size_t)orow*HSc+ox] = spb(acc);
}

// ---------------- forward row FFTs ----------------
__global__ void k_fftrows_prior(){
  __shared__ float2 sh[4*256];
  int line = blockIdx.x*4 + threadIdx.y;
  int t = threadIdx.x;
  float2* s = sh + threadIdx.y*256;
  float x = g_prior[(size_t)line*HSc+t];
  s[t]=make_float2(x,0.f);
  s[t+128]=make_float2(0.f,0.f);
  fft256(s,t,false);
  float2* dst = g_RP + (size_t)line*NH;
  dst[t]=s[t];
  if (!t) dst[128]=s[128];
}
__global__ void k_fftrows_like(const int* __restrict__ vidx){
  __shared__ float2 sh[4*256];
  int line = blockIdx.x*4 + threadIdx.y;
  int t = threadIdx.x;
  float2* s = sh + threadIdx.y*256;
  int img=line>>7, row=line&127;
  int b=img/NIMGP, lk=img%NIMGP;
  int c = vidx[lk];
  float x = spb(g_hmrs[(((size_t)(b*Lc+c))*HSc+row)*HSc+t]);
  s[t]=make_float2(x,0.f);
  s[t+128]=make_float2(0.f,0.f);
  fft256(s,t,false);
  float2* dst = g_RL + (size_t)line*NH;
  dst[t]=s[t];
  if (!t) dst[128]=s[128];
}

// ---------------- prior column FFT -> full spectrum ----------------
__global__ void k_cols_prior(){
  __shared__ float tre[128][9], tim[128][9];
  __shared__ float2 scr[8][256];
  int kx0 = blockIdx.x*8;
  int img = blockIdx.y;
  int nk = min(8, NH-kx0);
  int tid = threadIdx.x;
  const float2* src = g_RP + (size_t)img*HSc*NH;
  for (int i=tid;i<128*8;i+=1024){
    int r=i>>3, j=i&7;
    float2 v = (kx0+j<NH)? src[r*NH+kx0+j] : make_float2(0.f,0.f);
    tre[r][j]=v.x; tim[r][j]=v.y;
  }
  int lane=tid>>7, t=tid&127;
  float2* s = scr[lane];
  __syncthreads();
  s[t]=make_float2(tre[t][lane], tim[t][lane]);
  s[t+128]=make_float2(0.f,0.f);
  fft256(s,t,false);
  if (lane<nk){
    float2* dst = g_SP + ((size_t)img*NH+kx0+lane)*256;
    dst[t]=s[t]; dst[t+128]=s[t+128];
  }
}

// ---------------- like: col FFT * spectrum * inverse col FFT ----------------
__global__ void k_cols_like(){
  __shared__ float tre[128][9], tim[128][9];
  __shared__ float2 scr[8][256];
  int kx0 = blockIdx.x*8;
  int img = blockIdx.y;
  int imgp = img % NIMGP;
  int nk = min(8, NH-kx0);
  int tid = threadIdx.x;
  const float2* src = g_RL + (size_t)img*HSc*NH;
  for (int i=tid;i<128*8;i+=1024){
    int r=i>>3, j=i&7;
    float2 v = (kx0+j<NH)? src[r*NH+kx0+j] : make_float2(0.f,0.f);
    tre[r][j]=v.x; tim[r][j]=v.y;
  }
  int lane=tid>>7, t=tid&127;
  float2* s = scr[lane];
  __syncthreads();
  s[t]=make_float2(tre[t][lane], tim[t][lane]);
  s[t+128]=make_float2(0.f,0.f);
  fft256(s,t,false);
  if (lane<nk){
    const float2* sp = g_SP + ((size_t)imgp*NH+kx0+lane)*256;
    s[t]=cmul(s[t],sp[t]);
    s[t+128]=cmul(s[t+128],sp[t+128]);
  }
  fft256(s,t,true);
  tre[t][lane]=s[64+t].x; tim[t][lane]=s[64+t].y;
  __syncthreads();
  float2* dst = g_TL + (size_t)img*HSc*NH;
  for (int i=tid;i<128*8;i+=1024){
    int r=i>>3, j=i&7;
    if (kx0+j<NH) dst[r*NH+kx0+j]=make_float2(tre[r][j],tim[r][j]);
  }
}

// ---------------- inverse row FFT + log-energy over K ----------------
__global__ void k_energy(const float* __restrict__ bias){
  __shared__ float2 scr[8][256];
  __shared__ float ssum[8][128];
  int blr = blockIdx.x;            // bl*128+row
  int row = blr&127, bl = blr>>7;
  int l = bl % Lc;
  int tid = threadIdx.x;
  int lane = tid>>7, t = tid&127;  // lane = k
  int img = bl*Kc + lane;
  float2* s = scr[lane];
  const float2* src = g_TL + ((size_t)img*HSc+row)*NH;
  float2 v = src[t];
  s[t]=v;
  if (t) s[256-t]=make_float2(v.x,-v.y);
  else   s[128]=src[128];
  fft256(s,t,true);
  float conv = s[64+t].x*(1.f/65536.f);
  float bb = bias[(((size_t)(l*Kc+lane))*HSc+row)*HSc+t];
  ssum[lane][t] = logf(conv + spb(bb) + 1e-6f);
  __syncthreads();
  if (!lane){
    float e=0.f;
#pragma unroll
    for (int k=0;k<8;k++) e += ssum[k][t];
    g_energy128[(size_t)blr*HSc+t]=e;
  }
}

// ---------------- energy upsample 128->512 (x then y) + log(spb(hm)) + rowmax ----------------
__global__ void k_u1(){
  int r = blockIdx.x;              // bl*128+y
  int X = threadIdx.x;             // 512
  int s0 = g_wU128s[X];
  const float* src = g_energy128 + (size_t)r*HSc;
  float acc=0.f;
#pragma unroll
  for (int j=0;j<4;j++){
    int i = min(max(s0+j,0),HSc-1);
    acc = fmaf(g_wU128[X][j], src[i], acc);
  }
  g_tmpA[(size_t)r*HMc+X]=acc;
}
__global__ void k_u2(const float* __restrict__ heat, const float* __restrict__ beta){
  int rY = blockIdx.x;             // bl*512+Y
  int bl = rY>>9, Y = rY&511;
  int l = bl % Lc;
  int X = threadIdx.x;
  int s0 = g_wU128s[Y];
  float acc=0.f;
#pragma unroll
  for (int j=0;j<4;j++){
    int i = min(max(s0+j,0),HSc-1);
    acc = fmaf(g_wU128[Y][j], g_tmpA[((size_t)bl*HSc+i)*HMc+X], acc);
  }
  float h = heat[(size_t)rY*HMc+X];
  float hm = (h-g_mean[l])*g_scale[l]+beta[l];
  float e = acc + logf(spb(hm)+1e-6f);
  g_energy512[(size_t)rY*HMc+X]=e;
  __shared__ float sm[512];
  sm[X]=e; __syncthreads();
  for (int o=256;o>0;o>>=1){
    if (X<o) sm[X]=fmaxf(sm[X],sm[X+o]);
    __syncthreads();
  }
  if (!X) g_rowmax[rY]=sm[0];
}
__global__ void k_max(){
  int bl=blockIdx.x, t=threadIdx.x;
  __shared__ float sm[512];
  sm[t]=g_rowmax[bl*HMc+t]; __syncthreads();
  for (int o=256;o>0;o>>=1){
    if (t<o) sm[t]=fmaxf(sm[t],sm[t+o]);
    __syncthreads();
  }
  if (!t) g_maxv[bl]=sm[0];
}
__global__ void k_sumexp(){
  int rY = blockIdx.x;             // bl*512+Y
  int bl = rY>>9, Y = rY&511;
  int X = threadIdx.x;
  float e = g_energy512[(size_t)rY*HMc+X];
  float p = expf(e - g_maxv[bl]);
  __shared__ float sa[512], sb[512];
  sa[X]=p; sb[X]=p*(float)X; __syncthreads();
  for (int o=256;o>0;o>>=1){
    if (X<o){ sa[X]+=sa[X+o]; sb[X]+=sb[X+o]; }
    __syncthreads();
  }
  if (!X) g_part[rY]=make_float4(sa[0], sb[0], (float)Y*sa[0], 0.f);
}
__global__ void k_final(float* __restrict__ out){
  int bl=blockIdx.x, t=threadIdx.x;
  __shared__ float s0[512],s1[512],s2[512];
  float4 v = g_part[bl*HMc+t];
  s0[t]=v.x; s1[t]=v.y; s2[t]=v.z; __syncthreads();
  for (int o=256;o>0;o>>=1){
    if (t<o){ s0[t]+=s0[t+o]; s1[t]+=s1[t+o]; s2[t]+=s2[t+o]; }
    __syncthreads();
  }
  if (!t){
    out[bl*3+0]=1.f;
    out[bl*3+1]=s2[0]/s0[0];   // ex: row index (Y)
    out[bl*3+2]=s1[0]/s0[0];   // ey: col index (X)
  }
}

extern "C" void kernel_launch(void* const* d_in, const int* in_sizes, int n_in,
                              void* d_out, int out_size){
  const float* heat  = (const float*)d_in[0];
  const float* cond  = (const float*)d_in[1];
  const float* bias  = (const float*)d_in[2];
  const float* gamma = (const float*)d_in[3];
  const float* beta  = (const float*)d_in[4];
  const int*   vidx  = (const int*)d_in[5];
  float* out = (float*)d_out;

  k_setup<<<1,512>>>();
  k_bn_partial<<<dim3(Lc,32),256>>>(heat);
  k_bn_final<<<1,64>>>(gamma);
  k_r1<<<NBL*HMc,128>>>(heat, beta);
  k_r2<<<NBL*HSc,128>>>();
  k_prior<<<NIMGP*HSc,128>>>(cond);
  k_fftrows_prior<<<NIMGP*HSc/4, dim3(128,4)>>>();
  k_fftrows_like<<<NIMG*HSc/4, dim3(128,4)>>>(vidx);
  k_cols_prior<<<dim3(17,NIMGP),1024>>>();
  k_cols_like<<<dim3(17,NIMG),1024>>>();
  k_energy<<<NBL*HSc,1024>>>(bias);
  k_u1<<<NBL*HSc,512>>>();
  k_u2<<<NBL*HMc,512>>>(heat, beta);
  k_max<<<NBL,512>>>();
  k_sumexp<<<NBL*HMc,512>>>();
  k_final<<<NBL,512>>>(out);
}

// round 4
// speedup vs baseline: 2.4254x; 2.4254x over previous
#include <cuda_runtime.h>
#include <math.h>

#define Lc 37
#define Kc 8
#define HMc 512
#define HSc 128
#define HCc 64
#define Bc 2
#define NIMGP (Lc*Kc)     // 296 (l,k) pairs; both batches packed as complex
#define NBL   (Bc*Lc)     // 74
#define NFFT 256

// ---------------- device scratch ----------------
__device__ float  g_tmpA[NBL*HMc*HSc];      // r1 out [bl*512+y][128]; reused by u1 as [bl*128+y][512]
__device__ float  g_hmrs[NBL*HSc*HSc];
__device__ float  g_prior[NIMGP*HSc*HSc];
__device__ float2 g_RL[NIMGP*HSc*NFFT];     // like row spectra (packed b0+i*b1), 77.6MB
__device__ float2 g_RP[NIMGP*HSc*NFFT];     // prior row spectra
__device__ float2 g_SP[NIMGP*NFFT*NFFT];    // prior full 2D spectra [lk][kx][i], 155MB
__device__ float2 g_TL[NIMGP*HSc*NFFT];     // after col conv, [lk][y][kx]
__device__ float  g_energy128[NBL*HSc*HSc];
__device__ float2 g_bnp[Lc*32];
__device__ float  g_mean[Lc], g_scale[Lc];
__device__ float4 g_rs[NBL*HMc];            // per-row (max, sum, sumX, -)
__device__ float  g_wD[HSc][16];
__device__ float  g_wU64[HSc][4];
__device__ int    g_wU64s[HSc];
__device__ float  g_wU128[HMc][4];
__device__ int    g_wU128s[HMc];

// ---------------- helpers ----------------
__device__ __forceinline__ float2 cmulf(float2 a, float2 b){
  return make_float2(fmaf(a.x,b.x,-a.y*b.y), fmaf(a.x,b.y,a.y*b.x));
}
__device__ __forceinline__ float2 cadd(float2 a, float2 b){ return make_float2(a.x+b.x, a.y+b.y); }
__device__ __forceinline__ float2 csub(float2 a, float2 b){ return make_float2(a.x-b.x, a.y-b.y); }
__device__ __forceinline__ float2 tw(int e, float sgn){
  float s,c;
  __sincosf((float)e * -0.0245436926061702596f, &s, &c);  // -2*pi/256
  return make_float2(c, s*sgn);
}
__device__ __forceinline__ float2 shx2(float2 v, int m){
  return make_float2(__shfl_xor_sync(0xffffffffu, v.x, m),
                     __shfl_xor_sync(0xffffffffu, v.y, m));
}
__device__ __forceinline__ float spb(float x){
  float t = 5.f*x;
  return 0.2f*(fmaxf(t,0.f) + log1pf(__expf(-fabsf(t))));
}
__device__ double keysd(double x){
  if (x >= 2.0) return 0.0;
  if (x >= 1.0) return ((-0.5*x + 2.5)*x - 4.0)*x + 2.0;
  return ((1.5*x - 2.5)*x)*x + 1.0;
}

// 256-pt FFT, warp-collective: lane t holds v[j] = element (j*32+t).
// Forward DIF: natural input -> bit-reversed-position output.
__device__ __forceinline__ void fft_fwd(float2 v[8], int t){
  // h=128 (in-register, j-bit 2)
#pragma unroll
  for (int j=0;j<4;j++){
    float2 a=v[j], b=v[j+4];
    v[j]=cadd(a,b);
    v[j+4]=cmulf(csub(a,b), tw(j*32+t, 1.f));
  }
  // h=64 (j-bit 1)
#pragma unroll
  for (int g=0; g<8; g+=4){
#pragma unroll
    for (int j2=0;j2<2;j2++){
      int jl=g+j2, jh=g+j2+2;
      float2 a=v[jl], b=v[jh];
      v[jl]=cadd(a,b);
      v[jh]=cmulf(csub(a,b), tw((j2*32+t)*2, 1.f));
    }
  }
  // h=32 (j-bit 0)
  {
    float2 w = tw(t*4, 1.f);
#pragma unroll
    for (int p=0;p<8;p+=2){
      float2 a=v[p], b=v[p+1];
      v[p]=cadd(a,b);
      v[p+1]=cmulf(csub(a,b), w);
    }
  }
  // cross-lane h=16,8,4,2,1
#pragma unroll
  for (int hs=4; hs>=0; hs--){
    int h = 1<<hs;
    float2 w = tw((t & (h-1)) * (128>>hs), 1.f);
    bool up = (t & h) != 0;
#pragma unroll
    for (int j=0;j<8;j++){
      float2 o = shx2(v[j], h);
      v[j] = up ? cmulf(csub(o, v[j]), w) : cadd(v[j], o);
    }
  }
}
// Inverse DIT (unnormalized, x256): bit-reversed-position input -> natural output.
__device__ __forceinline__ void fft_inv(float2 v[8], int t){
#pragma unroll
  for (int hs=0; hs<=4; hs++){
    int h = 1<<hs;
    float2 w = tw((t & (h-1)) * (128>>hs), -1.f);
    bool up = (t & h) != 0;
#pragma unroll
    for (int j=0;j<8;j++){
      float2 o = shx2(v[j], h);
      v[j] = up ? csub(o, cmulf(v[j], w)) : cadd(v[j], cmulf(o, w));
    }
  }
  // h=32
  {
    float2 w = tw(t*4, -1.f);
#pragma unroll
    for (int p=0;p<8;p+=2){
      float2 a=v[p];
      float2 wb=cmulf(v[p+1], w);
      v[p]=cadd(a,wb); v[p+1]=csub(a,wb);
    }
  }
  // h=64
#pragma unroll
  for (int g=0; g<8; g+=4){
#pragma unroll
    for (int j2=0;j2<2;j2++){
      int jl=g+j2, jh=g+j2+2;
      float2 a=v[jl];
      float2 wb=cmulf(v[jh], tw((j2*32+t)*2, -1.f));
      v[jl]=cadd(a,wb); v[jh]=csub(a,wb);
    }
  }
  // h=128
#pragma unroll
  for (int j=0;j<4;j++){
    float2 a=v[j];
    float2 wb=cmulf(v[j+4], tw(j*32+t, -1.f));
    v[j]=cadd(a,wb); v[j+4]=csub(a,wb);
  }
}

// ---------------- setup (resize weight tables) ----------------
__global__ void k_setup(){
  int t = threadIdx.x;
  if (t < HSc){
    double sf = 4.0*t + 1.5;
    int s0 = 4*t - 6;
    double w[16], ws=0.0;
    for (int j=0;j<16;j++){
      int i=s0+j;
      double kv = keysd(fabs(sf-(double)i)*0.25);
      if (i<0 || i>511) kv=0.0;
      w[j]=kv; ws+=kv;
    }
    for (int j=0;j<16;j++) g_wD[t][j]=(float)(w[j]/ws);
    double sf2 = 0.5*t - 0.25;
    int b0 = (int)floor(sf2)-1;
    g_wU64s[t]=b0;
    double w4[4]; ws=0.0;
    for (int j=0;j<4;j++){
      int i=b0+j;
      double kv = keysd(fabs(sf2-(double)i));
      if (i<0||i>63) kv=0.0;
      w4[j]=kv; ws+=kv;
    }
    for (int j=0;j<4;j++) g_wU64[t][j]=(float)(w4[j]/ws);
  }
  if (t < HMc){
    double sf = 0.25*t - 0.375;
    int b0 = (int)floor(sf)-1;
    g_wU128s[t]=b0;
    double w4[4], ws=0.0;
    for (int j=0;j<4;j++){
      int i=b0+j;
      double kv = keysd(fabs(sf-(double)i));
      if (i<0||i>127) kv=0.0;
      w4[j]=kv; ws+=kv;
    }
    for (int j=0;j<4;j++) g_wU128[t][j]=(float)(w4[j]/ws);
  }
}

// ---------------- batchnorm ----------------
__global__ void k_bn_partial(const float* __restrict__ heat){
  int l = blockIdx.x, nb = blockIdx.y;
  const float* p0 = heat + (size_t)l*262144;
  const float* p1 = heat + (size_t)(Lc+l)*262144;
  float s=0.f, ss=0.f;
  int end=(nb+1)*16384;
  for (int i=threadIdx.x+nb*16384; i<end; i+=256){
    float v = (i<262144)? p0[i] : p1[i-262144];
    s+=v; ss=fmaf(v,v,ss);
  }
  __shared__ float sa[256], sb[256];
  sa[threadIdx.x]=s; sb[threadIdx.x]=ss; __syncthreads();
  for (int o=128;o>0;o>>=1){
    if (threadIdx.x<o){ sa[threadIdx.x]+=sa[threadIdx.x+o]; sb[threadIdx.x]+=sb[threadIdx.x+o]; }
    __syncthreads();
  }
  if (!threadIdx.x) g_bnp[l*32+nb]=make_float2(sa[0],sb[0]);
}
__global__ void k_bn_final(const float* __restrict__ gamma){
  int t=threadIdx.x;
  if (t<Lc){
    float s=0.f, ss=0.f;
    for (int j=0;j<32;j++){ float2 v=g_bnp[t*32+j]; s+=v.x; ss+=v.y; }
    const float N=524288.f;
    float mean=s/N, var=ss/N-mean*mean;
    g_mean[t]=mean;
    g_scale[t]=gamma[t]*rsqrtf(var+1e-5f);
  }
}

// ---------------- resize 512->128 x-pass (vectorized, BN folded) ----------------
__global__ void k_r1(const float* __restrict__ heat, const float* __restrict__ beta){
  int row = blockIdx.x;          // bl*512+y
  int bl = row>>9, l = bl % Lc;
  const float* src = heat + (size_t)row*HMc;
  float mean=g_mean[l], sc=g_scale[l], be=beta[l];
  int oc = threadIdx.x;
  float acc=0.f;
  if (oc>=2 && oc<126){
    const float4* s4 = (const float4*)src;
    float x[20];
#pragma unroll
    for (int d=0; d<5; d++){
      float4 f = s4[oc-2+d];
      x[4*d]=f.x; x[4*d+1]=f.y; x[4*d+2]=f.z; x[4*d+3]=f.w;
    }
#pragma unroll
    for (int j=0;j<16;j++) acc = fmaf(g_wD[oc][j], x[2+j], acc);
  } else {
    int s0 = 4*oc-6;
#pragma unroll
    for (int j=0;j<16;j++){
      int i = min(max(s0+j,0),HMc-1);
      acc = fmaf(g_wD[oc][j], src[i], acc);
    }
  }
  g_tmpA[(size_t)row*HSc+oc] = (acc-mean)*sc + be;
}
// y-pass
__global__ void k_r2(){
  int orow = blockIdx.x;         // bl*128+oy
  int bl = orow>>7, oy = orow&127;
  int oc = threadIdx.x;
  int s0 = 4*oy-6;
  float acc=0.f;
#pragma unroll
  for (int j=0;j<16;j++){
    int i = min(max(s0+j,0),HMc-1);
    acc = fmaf(g_wD[oy][j], g_tmpA[((size_t)bl*HMc+i)*HSc+oc], acc);
  }
  g_hmrs[(size_t)orow*HSc+oc] = acc;
}

// ---------------- prior = spb(upsample64->128(cond)) ----------------
__global__ void k_prior(const float* __restrict__ cond){
  int orow = blockIdx.x;         // lk*128+oy
  int lk = orow>>7, oy = orow&127;
  int ox = threadIdx.x;
  int sy=g_wU64s[oy], sx=g_wU64s[ox];
  const float* src = cond + (size_t)lk*HCc*HCc;
  float acc=0.f;
#pragma unroll
  for (int a=0;a<4;a++){
    int iy = min(max(sy+a,0),HCc-1);
    float r=0.f;
#pragma unroll
    for (int b2=0;b2<4;b2++){
      int ix = min(max(sx+b2,0),HCc-1);
      r = fmaf(g_wU64[ox][b2], src[iy*HCc+ix], r);
    }
    acc = fmaf(g_wU64[oy][a], r, acc);
  }
  g_prior[(size_t)orow*HSc+ox] = spb(acc);
}

// ---------------- row FFTs (warp per row, no syncs) ----------------
__global__ void k_rows_prior(){
  int gw = blockIdx.x*8 + (threadIdx.x>>5);  // lk*128+row
  int t = threadIdx.x & 31;
  const float* src = g_prior + (size_t)gw*HSc;
  float2 v[8];
#pragma unroll
  for (int j=0;j<8;j++) v[j] = (j<4)? make_float2(src[j*32+t],0.f) : make_float2(0.f,0.f);
  fft_fwd(v,t);
  float2* dst = g_RP + (size_t)gw*NFFT;
#pragma unroll
  for (int j=0;j<8;j++) dst[j*32+t]=v[j];
}
__global__ void k_rows_like(const int* __restrict__ vidx){
  int gw = blockIdx.x*8 + (threadIdx.x>>5);  // lk*128+row
  int t = threadIdx.x & 31;
  int lk = gw>>7, row = gw&127;
  int c = vidx[lk];
  const float* s0 = g_hmrs + (((size_t)c)*HSc+row)*HSc;          // b=0
  const float* s1 = g_hmrs + (((size_t)(Lc+c))*HSc+row)*HSc;     // b=1
  float2 v[8];
#pragma unroll
  for (int j=0;j<8;j++){
    if (j<4){ int x=j*32+t; v[j]=make_float2(spb(s0[x]), spb(s1[x])); }
    else v[j]=make_float2(0.f,0.f);
  }
  fft_fwd(v,t);
  float2* dst = g_RL + (size_t)gw*NFFT;
#pragma unroll
  for (int j=0;j<8;j++) dst[j*32+t]=v[j];
}

// ---------------- prior column FFTs -> full spectrum ----------------
__global__ void k_cols_prior(){
  __shared__ float2 tile[128][9];
  int kx0 = blockIdx.x*8;
  int lk = blockIdx.y;
  int tid = threadIdx.x;
  const float2* src = g_RP + (size_t)lk*HSc*NFFT;
  for (int i=tid;i<1024;i+=256){
    int r=i>>3, c=i&7;
    tile[r][c]=src[r*NFFT + kx0 + c];
  }
  __syncthreads();
  int w = tid>>5, t = tid&31;
  float2 v[8];
#pragma unroll
  for (int j=0;j<8;j++) v[j] = (j<4)? tile[j*32+t][w] : make_float2(0.f,0.f);
  fft_fwd(v,t);
  float2* dst = g_SP + ((size_t)lk*NFFT + kx0 + w)*NFFT;
#pragma unroll
  for (int j=0;j<8;j++) dst[j*32+t]=v[j];
}

// ---------------- like columns: FFT * spectrum * inverse FFT ----------------
__global__ void k_cols_like(){
  __shared__ float2 tile[128][9];
  int kx0 = blockIdx.x*8;
  int lk = blockIdx.y;
  int tid = threadIdx.x;
  const float2* src = g_RL + (size_t)lk*HSc*NFFT;
  for (int i=tid;i<1024;i+=256){
    int r=i>>3, c=i&7;
    tile[r][c]=src[r*NFFT + kx0 + c];
  }
  __syncthreads();
  int w = tid>>5, t = tid&31;
  float2 v[8];
#pragma unroll
  for (int j=0;j<8;j++) v[j] = (j<4)? tile[j*32+t][w] : make_float2(0.f,0.f);
  fft_fwd(v,t);
  const float2* sp = g_SP + ((size_t)lk*NFFT + kx0 + w)*NFFT;
#pragma unroll
  for (int j=0;j<8;j++) v[j]=cmulf(v[j], sp[j*32+t]);
  fft_inv(v,t);
  // keep spatial y = 64..191 (elements j=2..5)
#pragma unroll
  for (int j=2;j<6;j++) tile[(j-2)*32+t][w]=v[j];
  __syncthreads();
  float2* dst = g_TL + (size_t)lk*HSc*NFFT;
  for (int i=tid;i<1024;i+=256){
    int r=i>>3, c=i&7;
    dst[r*NFFT + kx0 + c]=tile[r][c];
  }
}

// ---------------- inverse row FFT + log-energy over K (both batches) ----------------
__global__ void k_energy(const float* __restrict__ bias){
  __shared__ float sm0[8][128], sm1[8][128];
  int ly = blockIdx.x;             // l*128+y
  int y = ly&127, l = ly>>7;
  int tid = threadIdx.x;
  int k = tid>>5, t = tid&31;
  int lk = l*Kc + k;
  const float2* src = g_TL + ((size_t)lk*HSc + y)*NFFT;
  float2 v[8];
#pragma unroll
  for (int j=0;j<8;j++) v[j]=src[j*32+t];
  fft_inv(v,t);
  const float sc = 1.f/65536.f;
  const float* bi = bias + ((size_t)lk*HSc + y)*HSc;
#pragma unroll
  for (int j=2;j<6;j++){
    int x = (j-2)*32 + t;
    float sb = spb(bi[x]);
    sm0[k][x] = logf(fmaf(v[j].x, sc, sb) + 1e-6f);
    sm1[k][x] = logf(fmaf(v[j].y, sc, sb) + 1e-6f);
  }
  __syncthreads();
  if (tid < 128){
    float e=0.f;
#pragma unroll
    for (int kk=0;kk<8;kk++) e += sm0[kk][tid];
    g_energy128[(((size_t)l)*HSc+y)*HSc+tid]=e;               // b=0 (bl=l)
  } else {
    int x = tid-128;
    float e=0.f;
#pragma unroll
    for (int kk=0;kk<8;kk++) e += sm1[kk][x];
    g_energy128[(((size_t)(Lc+l))*HSc+y)*HSc+x]=e;            // b=1 (bl=37+l)
  }
}

// ---------------- upsample 128->512 x-pass ----------------
__global__ void k_u1(){
  int r = blockIdx.x;              // bl*128+y
  int X = threadIdx.x;
  int s0 = g_wU128s[X];
  const float* src = g_energy128 + (size_t)r*HSc;
  float acc=0.f;
#pragma unroll
  for (int j=0;j<4;j++){
    int i = min(max(s0+j,0),HSc-1);
    acc = fmaf(g_wU128[X][j], src[i], acc);
  }
  g_tmpA[(size_t)r*HMc+X]=acc;
}
// y-pass + log(spb(hm)) + per-row softmax stats (no energy512 store)
__global__ void k_u2(const float* __restrict__ heat, const float* __restrict__ beta){
  int rY = blockIdx.x;             // bl*512+Y
  int bl = rY>>9, Y = rY&511;
  int l = bl % Lc;
  int X = threadIdx.x;
  int s0 = g_wU128s[Y];
  float acc=0.f;
#pragma unroll
  for (int j=0;j<4;j++){
    int i = min(max(s0+j,0),HSc-1);
    acc = fmaf(g_wU128[Y][j], g_tmpA[((size_t)bl*HSc+i)*HMc+X], acc);
  }
  float h = heat[(size_t)rY*HMc+X];
  float hm = (h-g_mean[l])*g_scale[l]+beta[l];
  float e = acc + logf(spb(hm)+1e-6f);
  __shared__ float sa[512], sb[512];
  sa[X]=e; __syncthreads();
  for (int o=256;o>0;o>>=1){
    if (X<o) sa[X]=fmaxf(sa[X],sa[X+o]);
    __syncthreads();
  }
  float m = sa[0];
  __syncthreads();
  float p = __expf(e - m);
  sa[X]=p; sb[X]=p*(float)X; __syncthreads();
  for (int o=256;o>0;o>>=1){
    if (X<o){ sa[X]+=sa[X+o]; sb[X]+=sb[X+o]; }
    __syncthreads();
  }
  if (!X) g_rs[rY]=make_float4(m, sa[0], sb[0], 0.f);
}
__global__ void k_final(float* __restrict__ out){
  int bl=blockIdx.x, t=threadIdx.x;
  float4 v = g_rs[bl*HMc+t];
  __shared__ float sm[512];
  sm[t]=v.x; __syncthreads();
  for (int o=256;o>0;o>>=1){
    if (t<o) sm[t]=fmaxf(sm[t],sm[t+o]);
    __syncthreads();
  }
  float gmax = sm[0];
  __syncthreads();
  float w = __expf(v.x - gmax);
  __shared__ float s0[512], s1[512], s2[512];
  s0[t]=v.y*w; s1[t]=v.z*w; s2[t]=(float)t*v.y*w;
  __syncthreads();
  for (int o=256;o>0;o>>=1){
    if (t<o){ s0[t]+=s0[t+o]; s1[t]+=s1[t+o]; s2[t]+=s2[t+o]; }
    __syncthreads();
  }
  if (!t){
    out[bl*3+0]=1.f;
    out[bl*3+1]=s2[0]/s0[0];   // ex (row index Y)
    out[bl*3+2]=s1[0]/s0[0];   // ey (col index X)
  }
}

extern "C" void kernel_launch(void* const* d_in, const int* in_sizes, int n_in,
                              void* d_out, int out_size){
  const float* heat  = (const float*)d_in[0];
  const float* cond  = (const float*)d_in[1];
  const float* bias  = (const float*)d_in[2];
  const float* gamma = (const float*)d_in[3];
  const float* beta  = (const float*)d_in[4];
  const int*   vidx  = (const int*)d_in[5];
  float* out = (float*)d_out;

  k_setup<<<1,512>>>();
  k_bn_partial<<<dim3(Lc,32),256>>>(heat);
  k_bn_final<<<1,64>>>(gamma);
  k_r1<<<NBL*HMc,128>>>(heat, beta);
  k_r2<<<NBL*HSc,128>>>();
  k_prior<<<NIMGP*HSc,128>>>(cond);
  k_rows_prior<<<NIMGP*HSc/8,256>>>();
  k_rows_like<<<NIMGP*HSc/8,256>>>(vidx);
  k_cols_prior<<<dim3(32,NIMGP),256>>>();
  k_cols_like<<<dim3(32,NIMGP),256>>>();
  k_energy<<<Lc*HSc,256>>>(bias);
  k_u1<<<NBL*HSc,512>>>();
  k_u2<<<NBL*HMc,512>>>(heat, beta);
  k_final<<<NBL,512>>>(out);
}

// round 5
// speedup vs baseline: 3.3979x; 1.4010x over previous
#include <cuda_runtime.h>
#include <math.h>

#define Lc 37
#define Kc 8
#define HMc 512
#define HSc 128
#define HCc 64
#define Bc 2
#define NIMGP (Lc*Kc)     // 296 (l,k) pairs; batches packed as complex
#define NBL   (Bc*Lc)     // 74
#define NFFT 256

// ---------------- device scratch ----------------
__device__ float  g_tmpA[NBL*HMc*HSc];      // r1 out [bl*512+y][128]; reused by u1 as [bl*128+y][512]
__device__ float  g_hmrs[NBL*HSc*HSc];
__device__ float  g_prior[NIMGP*HSc*HSc];
__device__ float2 g_RL[NIMGP*HSc*NFFT];     // like row spectra (b0 + i*b1)
__device__ float2 g_RP[NIMGP*HSc*NFFT];     // prior row spectra
__device__ float2 g_TL[NIMGP*HSc*NFFT];     // after column conv, [lk][y][kx]
__device__ float  g_energy128[NBL*HSc*HSc];
__device__ float2 g_bnp[Lc*32];
__device__ float  g_mean[Lc], g_scale[Lc];
__device__ float4 g_rs[NBL*HMc];            // per-row (max, sum, sumX, -)
__device__ float  g_wDT[16][HSc];           // transposed: [tap][out-pos]
__device__ float  g_wU64T[4][HSc];
__device__ int    g_wU64s[HSc];
__device__ float  g_wU128T[4][HMc];
__device__ int    g_wU128s[HMc];

// ---------------- helpers ----------------
__device__ __forceinline__ float2 cmulf(float2 a, float2 b){
  return make_float2(fmaf(a.x,b.x,-a.y*b.y), fmaf(a.x,b.y,a.y*b.x));
}
__device__ __forceinline__ float2 cadd(float2 a, float2 b){ return make_float2(a.x+b.x, a.y+b.y); }
__device__ __forceinline__ float2 csub(float2 a, float2 b){ return make_float2(a.x-b.x, a.y-b.y); }
__device__ __forceinline__ float2 tw(int e, float sgn){
  float s,c;
  __sincosf((float)e * -0.0245436926061702596f, &s, &c);  // -2*pi/256
  return make_float2(c, s*sgn);
}
__device__ __forceinline__ float2 shx2(float2 v, int m){
  return make_float2(__shfl_xor_sync(0xffffffffu, v.x, m),
                     __shfl_xor_sync(0xffffffffu, v.y, m));
}
__device__ __forceinline__ float spb(float x){
  float t = 5.f*x;
  return 0.2f*(fmaxf(t,0.f) + log1pf(__expf(-fabsf(t))));
}
__device__ double keysd(double x){
  if (x >= 2.0) return 0.0;
  if (x >= 1.0) return ((-0.5*x + 2.5)*x - 4.0)*x + 2.0;
  return ((1.5*x - 2.5)*x)*x + 1.0;
}

// 256-pt FFT, warp-collective: lane t holds v[j] = element (j*32+t).
__device__ __forceinline__ void fft_fwd(float2 v[8], int t){
#pragma unroll
  for (int j=0;j<4;j++){
    float2 a=v[j], b=v[j+4];
    v[j]=cadd(a,b);
    v[j+4]=cmulf(csub(a,b), tw(j*32+t, 1.f));
  }
#pragma unroll
  for (int g=0; g<8; g+=4){
#pragma unroll
    for (int j2=0;j2<2;j2++){
      int jl=g+j2, jh=g+j2+2;
      float2 a=v[jl], b=v[jh];
      v[jl]=cadd(a,b);
      v[jh]=cmulf(csub(a,b), tw((j2*32+t)*2, 1.f));
    }
  }
  {
    float2 w = tw(t*4, 1.f);
#pragma unroll
    for (int p=0;p<8;p+=2){
      float2 a=v[p], b=v[p+1];
      v[p]=cadd(a,b);
      v[p+1]=cmulf(csub(a,b), w);
    }
  }
#pragma unroll
  for (int hs=4; hs>=0; hs--){
    int h = 1<<hs;
    float2 w = tw((t & (h-1)) * (128>>hs), 1.f);
    bool up = (t & h) != 0;
#pragma unroll
    for (int j=0;j<8;j++){
      float2 o = shx2(v[j], h);
      v[j] = up ? cmulf(csub(o, v[j]), w) : cadd(v[j], o);
    }
  }
}
__device__ __forceinline__ void fft_inv(float2 v[8], int t){
#pragma unroll
  for (int hs=0; hs<=4; hs++){
    int h = 1<<hs;
    float2 w = tw((t & (h-1)) * (128>>hs), -1.f);
    bool up = (t & h) != 0;
#pragma unroll
    for (int j=0;j<8;j++){
      float2 o = shx2(v[j], h);
      v[j] = up ? csub(o, cmulf(v[j], w)) : cadd(v[j], cmulf(o, w));
    }
  }
  {
    float2 w = tw(t*4, -1.f);
#pragma unroll
    for (int p=0;p<8;p+=2){
      float2 a=v[p];
      float2 wb=cmulf(v[p+1], w);
      v[p]=cadd(a,wb); v[p+1]=csub(a,wb);
    }
  }
#pragma unroll
  for (int g=0; g<8; g+=4){
#pragma unroll
    for (int j2=0;j2<2;j2++){
      int jl=g+j2, jh=g+j2+2;
      float2 a=v[jl];
      float2 wb=cmulf(v[jh], tw((j2*32+t)*2, -1.f));
      v[jl]=cadd(a,wb); v[jh]=csub(a,wb);
    }
  }
#pragma unroll
  for (int j=0;j<4;j++){
    float2 a=v[j];
    float2 wb=cmulf(v[j+4], tw(j*32+t, -1.f));
    v[j]=cadd(a,wb); v[j+4]=csub(a,wb);
  }
}

// block reductions (512 threads)
__device__ __forceinline__ float bredmax(float v, float* sh16){
#pragma unroll
  for (int m=16;m;m>>=1) v = fmaxf(v, __shfl_xor_sync(0xffffffffu, v, m));
  if (!(threadIdx.x&31)) sh16[threadIdx.x>>5]=v;
  __syncthreads();
  float r = sh16[0];
#pragma unroll
  for (int i=1;i<16;i++) r = fmaxf(r, sh16[i]);
  __syncthreads();
  return r;
}
__device__ __forceinline__ float bredsum(float v, float* sh16){
#pragma unroll
  for (int m=16;m;m>>=1) v += __shfl_xor_sync(0xffffffffu, v, m);
  if (!(threadIdx.x&31)) sh16[threadIdx.x>>5]=v;
  __syncthreads();
  float r = 0.f;
#pragma unroll
  for (int i=0;i<16;i++) r += sh16[i];
  __syncthreads();
  return r;
}

// ---------------- setup ----------------
__global__ void k_setup(){
  int t = threadIdx.x;
  if (t < HSc){
    double sf = 4.0*t + 1.5;
    int s0 = 4*t - 6;
    double w[16], ws=0.0;
    for (int j=0;j<16;j++){
      int i=s0+j;
      double kv = keysd(fabs(sf-(double)i)*0.25);
      if (i<0 || i>511) kv=0.0;
      w[j]=kv; ws+=kv;
    }
    for (int j=0;j<16;j++) g_wDT[j][t]=(float)(w[j]/ws);
    double sf2 = 0.5*t - 0.25;
    int b0 = (int)floor(sf2)-1;
    g_wU64s[t]=b0;
    double w4[4]; ws=0.0;
    for (int j=0;j<4;j++){
      int i=b0+j;
      double kv = keysd(fabs(sf2-(double)i));
      if (i<0||i>63) kv=0.0;
      w4[j]=kv; ws+=kv;
    }
    for (int j=0;j<4;j++) g_wU64T[j][t]=(float)(w4[j]/ws);
  }
  if (t < HMc){
    double sf = 0.25*t - 0.375;
    int b0 = (int)floor(sf)-1;
    g_wU128s[t]=b0;
    double w4[4], ws=0.0;
    for (int j=0;j<4;j++){
      int i=b0+j;
      double kv = keysd(fabs(sf-(double)i));
      if (i<0||i>127) kv=0.0;
      w4[j]=kv; ws+=kv;
    }
    for (int j=0;j<4;j++) g_wU128T[j][t]=(float)(w4[j]/ws);
  }
}

// ---------------- batchnorm ----------------
__global__ void k_bn_partial(const float* __restrict__ heat){
  int l = blockIdx.x, nb = blockIdx.y;
  const float* p0 = heat + (size_t)l*262144;
  const float* p1 = heat + (size_t)(Lc+l)*262144;
  float s=0.f, ss=0.f;
  int end=(nb+1)*16384;
  for (int i=threadIdx.x+nb*16384; i<end; i+=256){
    float v = (i<262144)? p0[i] : p1[i-262144];
    s+=v; ss=fmaf(v,v,ss);
  }
  __shared__ float sa[256], sb[256];
  sa[threadIdx.x]=s; sb[threadIdx.x]=ss; __syncthreads();
  for (int o=128;o>0;o>>=1){
    if (threadIdx.x<o){ sa[threadIdx.x]+=sa[threadIdx.x+o]; sb[threadIdx.x]+=sb[threadIdx.x+o]; }
    __syncthreads();
  }
  if (!threadIdx.x) g_bnp[l*32+nb]=make_float2(sa[0],sb[0]);
}
__global__ void k_bn_final(const float* __restrict__ gamma){
  int t=threadIdx.x;
  if (t<Lc){
    float s=0.f, ss=0.f;
    for (int j=0;j<32;j++){ float2 v=g_bnp[t*32+j]; s+=v.x; ss+=v.y; }
    const float N=524288.f;
    float mean=s/N, var=ss/N-mean*mean;
    g_mean[t]=mean;
    g_scale[t]=gamma[t]*rsqrtf(var+1e-5f);
  }
}

// ---------------- resize 512->128 x-pass (BN folded, coalesced weights) ----------------
__global__ void k_r1(const float* __restrict__ heat, const float* __restrict__ beta){
  int row = blockIdx.x;          // bl*512+y
  int bl = row>>9, l = bl % Lc;
  const float* src = heat + (size_t)row*HMc;
  float mean=g_mean[l], sc=g_scale[l], be=beta[l];
  int oc = threadIdx.x;
  float acc=0.f;
  if (oc>=2 && oc<126){
    const float4* s4 = (const float4*)src;
    float x[20];
#pragma unroll
    for (int d=0; d<5; d++){
      float4 f = s4[oc-2+d];
      x[4*d]=f.x; x[4*d+1]=f.y; x[4*d+2]=f.z; x[4*d+3]=f.w;
    }
#pragma unroll
    for (int j=0;j<16;j++) acc = fmaf(g_wDT[j][oc], x[2+j], acc);
  } else {
    int s0 = 4*oc-6;
#pragma unroll
    for (int j=0;j<16;j++){
      int i = min(max(s0+j,0),HMc-1);
      acc = fmaf(g_wDT[j][oc], src[i], acc);
    }
  }
  g_tmpA[(size_t)row*HSc+oc] = (acc-mean)*sc + be;
}
// y-pass (weights broadcast: oy uniform per block)
__global__ void k_r2(){
  int orow = blockIdx.x;         // bl*128+oy
  int bl = orow>>7, oy = orow&127;
  int oc = threadIdx.x;
  int s0 = 4*oy-6;
  float acc=0.f;
#pragma unroll
  for (int j=0;j<16;j++){
    int i = min(max(s0+j,0),HMc-1);
    acc = fmaf(g_wDT[j][oy], g_tmpA[((size_t)bl*HMc+i)*HSc+oc], acc);
  }
  g_hmrs[(size_t)orow*HSc+oc] = acc;
}

// ---------------- prior = spb(upsample64->128(cond)) ----------------
__global__ void k_prior(const float* __restrict__ cond){
  int orow = blockIdx.x;         // lk*128+oy
  int lk = orow>>7, oy = orow&127;
  int ox = threadIdx.x;
  int sy=g_wU64s[oy], sx=g_wU64s[ox];
  const float* src = cond + (size_t)lk*HCc*HCc;
  float wx[4];
#pragma unroll
  for (int j=0;j<4;j++) wx[j]=g_wU64T[j][ox];
  float acc=0.f;
#pragma unroll
  for (int a=0;a<4;a++){
    int iy = min(max(sy+a,0),HCc-1);
    float r=0.f;
#pragma unroll
    for (int b2=0;b2<4;b2++){
      int ix = min(max(sx+b2,0),HCc-1);
      r = fmaf(wx[b2], src[iy*HCc+ix], r);
    }
    acc = fmaf(g_wU64T[a][oy], r, acc);
  }
  g_prior[(size_t)orow*HSc+ox] = spb(acc);
}

// ---------------- row FFTs (warp per row) ----------------
__global__ void k_rows_prior(){
  int gw = blockIdx.x*8 + (threadIdx.x>>5);  // lk*128+row
  int t = threadIdx.x & 31;
  const float* src = g_prior + (size_t)gw*HSc;
  float2 v[8];
#pragma unroll
  for (int j=0;j<8;j++) v[j] = (j<4)? make_float2(src[j*32+t],0.f) : make_float2(0.f,0.f);
  fft_fwd(v,t);
  float2* dst = g_RP + (size_t)gw*NFFT;
#pragma unroll
  for (int j=0;j<8;j++) dst[j*32+t]=v[j];
}
__global__ void k_rows_like(const int* __restrict__ vidx){
  int gw = blockIdx.x*8 + (threadIdx.x>>5);  // lk*128+row
  int t = threadIdx.x & 31;
  int lk = gw>>7, row = gw&127;
  int c = vidx[lk];
  const float* s0 = g_hmrs + (((size_t)c)*HSc+row)*HSc;
  const float* s1 = g_hmrs + (((size_t)(Lc+c))*HSc+row)*HSc;
  float2 v[8];
#pragma unroll
  for (int j=0;j<8;j++){
    if (j<4){ int x=j*32+t; v[j]=make_float2(spb(s0[x]), spb(s1[x])); }
    else v[j]=make_float2(0.f,0.f);
  }
  fft_fwd(v,t);
  float2* dst = g_RL + (size_t)gw*NFFT;
#pragma unroll
  for (int j=0;j<8;j++) dst[j*32+t]=v[j];
}

// ---------------- columns: priorFFT x likeFFT -> inverse (fused, no g_SP) ----------------
__global__ void k_cols_conv(){
  __shared__ float2 tl[128][9];
  __shared__ float2 tp[128][9];
  int kx0 = blockIdx.x*8;
  int lk = blockIdx.y;
  int tid = threadIdx.x;
  const float2* srcL = g_RL + (size_t)lk*HSc*NFFT;
  const float2* srcP = g_RP + (size_t)lk*HSc*NFFT;
  for (int i=tid;i<1024;i+=256){
    int r=i>>3, c=i&7;
    tl[r][c]=srcL[r*NFFT + kx0 + c];
    tp[r][c]=srcP[r*NFFT + kx0 + c];
  }
  __syncthreads();
  int w = tid>>5, t = tid&31;
  float2 vp[8], v[8];
#pragma unroll
  for (int j=0;j<8;j++){
    vp[j] = (j<4)? tp[j*32+t][w] : make_float2(0.f,0.f);
    v[j]  = (j<4)? tl[j*32+t][w] : make_float2(0.f,0.f);
  }
  fft_fwd(vp,t);
  fft_fwd(v,t);
#pragma unroll
  for (int j=0;j<8;j++) v[j]=cmulf(v[j], vp[j]);
  fft_inv(v,t);
  // keep spatial y = 64..191 (j=2..5)
#pragma unroll
  for (int j=2;j<6;j++) tl[(j-2)*32+t][w]=v[j];
  __syncthreads();
  float2* dst = g_TL + (size_t)lk*HSc*NFFT;
  for (int i=tid;i<1024;i+=256){
    int r=i>>3, c=i&7;
    dst[r*NFFT + kx0 + c]=tl[r][c];
  }
}

// ---------------- inverse row FFT + log-energy over K (both batches) ----------------
__global__ void k_energy(const float* __restrict__ bias){
  __shared__ float sm0[8][128], sm1[8][128];
  int ly = blockIdx.x;             // l*128+y
  int y = ly&127, l = ly>>7;
  int tid = threadIdx.x;
  int k = tid>>5, t = tid&31;
  int lk = l*Kc + k;
  const float2* src = g_TL + ((size_t)lk*HSc + y)*NFFT;
  float2 v[8];
#pragma unroll
  for (int j=0;j<8;j++) v[j]=src[j*32+t];
  fft_inv(v,t);
  const float sc = 1.f/65536.f;
  const float* bi = bias + ((size_t)lk*HSc + y)*HSc;
#pragma unroll
  for (int j=2;j<6;j++){
    int x = (j-2)*32 + t;
    float sb = spb(bi[x]);
    sm0[k][x] = logf(fmaf(v[j].x, sc, sb) + 1e-6f);
    sm1[k][x] = logf(fmaf(v[j].y, sc, sb) + 1e-6f);
  }
  __syncthreads();
  if (tid < 128){
    float e=0.f;
#pragma unroll
    for (int kk=0;kk<8;kk++) e += sm0[kk][tid];
    g_energy128[(((size_t)l)*HSc+y)*HSc+tid]=e;
  } else {
    int x = tid-128;
    float e=0.f;
#pragma unroll
    for (int kk=0;kk<8;kk++) e += sm1[kk][x];
    g_energy128[(((size_t)(Lc+l))*HSc+y)*HSc+x]=e;
  }
}

// ---------------- upsample 128->512 x-pass ----------------
__global__ void k_u1(){
  int r = blockIdx.x;              // bl*128+y
  int X = threadIdx.x;
  int s0 = g_wU128s[X];
  const float* src = g_energy128 + (size_t)r*HSc;
  float acc=0.f;
#pragma unroll
  for (int j=0;j<4;j++){
    int i = min(max(s0+j,0),HSc-1);
    acc = fmaf(g_wU128T[j][X], src[i], acc);
  }
  g_tmpA[(size_t)r*HMc+X]=acc;
}
// y-pass + log(spb(hm)) + per-row softmax stats
__global__ void k_u2(const float* __restrict__ heat, const float* __restrict__ beta){
  int rY = blockIdx.x;             // bl*512+Y
  int bl = rY>>9, Y = rY&511;
  int l = bl % Lc;
  int X = threadIdx.x;
  int s0 = g_wU128s[Y];
  float acc=0.f;
#pragma unroll
  for (int j=0;j<4;j++){
    int i = min(max(s0+j,0),HSc-1);
    acc = fmaf(g_wU128T[j][Y], g_tmpA[((size_t)bl*HSc+i)*HMc+X], acc);
  }
  float h = heat[(size_t)rY*HMc+X];
  float hm = (h-g_mean[l])*g_scale[l]+beta[l];
  float e = acc + logf(spb(hm)+1e-6f);
  __shared__ float sh16[16];
  float m = bredmax(e, sh16);
  float p = __expf(e - m);
  float s = bredsum(p, sh16);
  float sx = bredsum(p*(float)X, sh16);
  if (!X) g_rs[rY]=make_float4(m, s, sx, 0.f);
}
__global__ void k_final(float* __restrict__ out){
  int bl=blockIdx.x, t=threadIdx.x;
  float4 v = g_rs[bl*HMc+t];
  __shared__ float sh16[16];
  float gmax = bredmax(v.x, sh16);
  float w = __expf(v.x - gmax);
  float s0 = bredsum(v.y*w, sh16);
  float s1 = bredsum(v.z*w, sh16);
  float s2 = bredsum((float)t*v.y*w, sh16);
  if (!t){
    out[bl*3+0]=1.f;
    out[bl*3+1]=s2/s0;   // ex (row index Y)
    out[bl*3+2]=s1/s0;   // ey (col index X)
  }
}

extern "C" void kernel_launch(void* const* d_in, const int* in_sizes, int n_in,
                              void* d_out, int out_size){
  const float* heat  = (const float*)d_in[0];
  const float* cond  = (const float*)d_in[1];
  const float* bias  = (const float*)d_in[2];
  const float* gamma = (const float*)d_in[3];
  const float* beta  = (const float*)d_in[4];
  const int*   vidx  = (const int*)d_in[5];
  float* out = (float*)d_out;

  k_setup<<<1,512>>>();
  k_bn_partial<<<dim3(Lc,32),256>>>(heat);
  k_bn_final<<<1,64>>>(gamma);
  k_r1<<<NBL*HMc,128>>>(heat, beta);
  k_r2<<<NBL*HSc,128>>>();
  k_prior<<<NIMGP*HSc,128>>>(cond);
  k_rows_prior<<<NIMGP*HSc/8,256>>>();
  k_rows_like<<<NIMGP*HSc/8,256>>>(vidx);
  k_cols_conv<<<dim3(32,NIMGP),256>>>();
  k_energy<<<Lc*HSc,256>>>(bias);
  k_u1<<<NBL*HSc,512>>>();
  k_u2<<<NBL*HMc,512>>>(heat, beta);
  k_final<<<NBL,512>>>(out);
}

// round 6
// speedup vs baseline: 3.4220x; 1.0071x over previous
#include <cuda_runtime.h>
#include <math.h>

#define Lc 37
#define Kc 8
#define HMc 512
#define HSc 128
#define HCc 64
#define Bc 2
#define NIMGP (Lc*Kc)     // 296
#define NBL   (Bc*Lc)     // 74
#define NFFT 256
#define LKSPLIT 144       // chunk0 lk [0,144) = l [0,18); chunk1 [144,296)
#define LSPLIT  18

// ---------------- device scratch ----------------
__device__ float  g_tmpA[NBL*HMc*HSc];      // r1 out (raw resize); reused by u1
__device__ float  g_hmrs[NBL*HSc*HSc];      // raw 128x128 resize
__device__ float  g_prior[NIMGP*HSc*HSc];
__device__ float2 g_RL[NIMGP*HSc*NFFT];
__device__ float2 g_RP[NIMGP*HSc*NFFT];
__device__ float2 g_TL[NIMGP*HSc*NFFT];
__device__ float  g_energy128[NBL*HSc*HSc];
__device__ float2 g_rowbn[NBL*HMc];         // per-row (sum, sumsq)
__device__ float  g_scale[Lc], g_bofs[Lc];
__device__ float4 g_rs[NBL*HMc];
__device__ float  g_wDT[16][HSc];
__device__ float  g_wU64T[4][HSc];
__device__ int    g_wU64s[HSc];
__device__ float  g_wU128T[4][HMc];
__device__ int    g_wU128s[HMc];

// ---------------- helpers ----------------
__device__ __forceinline__ float2 cmulf(float2 a, float2 b){
  return make_float2(fmaf(a.x,b.x,-a.y*b.y), fmaf(a.x,b.y,a.y*b.x));
}
__device__ __forceinline__ float2 cadd(float2 a, float2 b){ return make_float2(a.x+b.x, a.y+b.y); }
__device__ __forceinline__ float2 csub(float2 a, float2 b){ return make_float2(a.x-b.x, a.y-b.y); }
__device__ __forceinline__ float2 tw(int e, float sgn){
  float s,c;
  __sincosf((float)e * -0.0245436926061702596f, &s, &c);
  return make_float2(c, s*sgn);
}
__device__ __forceinline__ float2 shx2(float2 v, int m){
  return make_float2(__shfl_xor_sync(0xffffffffu, v.x, m),
                     __shfl_xor_sync(0xffffffffu, v.y, m));
}
__device__ __forceinline__ float spb(float x){
  float t = 5.f*x;
  return 0.2f*(fmaxf(t,0.f) + log1pf(__expf(-fabsf(t))));
}
__device__ double keysd(double x){
  if (x >= 2.0) return 0.0;
  if (x >= 1.0) return ((-0.5*x + 2.5)*x - 4.0)*x + 2.0;
  return ((1.5*x - 2.5)*x)*x + 1.0;
}

__device__ __forceinline__ void fft_fwd(float2 v[8], int t){
#pragma unroll
  for (int j=0;j<4;j++){
    float2 a=v[j], b=v[j+4];
    v[j]=cadd(a,b);
    v[j+4]=cmulf(csub(a,b), tw(j*32+t, 1.f));
  }
#pragma unroll
  for (int g=0; g<8; g+=4){
#pragma unroll
    for (int j2=0;j2<2;j2++){
      int jl=g+j2, jh=g+j2+2;
      float2 a=v[jl], b=v[jh];
      v[jl]=cadd(a,b);
      v[jh]=cmulf(csub(a,b), tw((j2*32+t)*2, 1.f));
    }
  }
  {
    float2 w = tw(t*4, 1.f);
#pragma unroll
    for (int p=0;p<8;p+=2){
      float2 a=v[p], b=v[p+1];
      v[p]=cadd(a,b);
      v[p+1]=cmulf(csub(a,b), w);
    }
  }
#pragma unroll
  for (int hs=4; hs>=0; hs--){
    int h = 1<<hs;
    float2 w = tw((t & (h-1)) * (128>>hs), 1.f);
    bool up = (t & h) != 0;
#pragma unroll
    for (int j=0;j<8;j++){
      float2 o = shx2(v[j], h);
      v[j] = up ? cmulf(csub(o, v[j]), w) : cadd(v[j], o);
    }
  }
}
__device__ __forceinline__ void fft_inv(float2 v[8], int t){
#pragma unroll
  for (int hs=0; hs<=4; hs++){
    int h = 1<<hs;
    float2 w = tw((t & (h-1)) * (128>>hs), -1.f);
    bool up = (t & h) != 0;
#pragma unroll
    for (int j=0;j<8;j++){
      float2 o = shx2(v[j], h);
      v[j] = up ? csub(o, cmulf(v[j], w)) : cadd(v[j], cmulf(o, w));
    }
  }
  {
    float2 w = tw(t*4, -1.f);
#pragma unroll
    for (int p=0;p<8;p+=2){
      float2 a=v[p];
      float2 wb=cmulf(v[p+1], w);
      v[p]=cadd(a,wb); v[p+1]=csub(a,wb);
    }
  }
#pragma unroll
  for (int g=0; g<8; g+=4){
#pragma unroll
    for (int j2=0;j2<2;j2++){
      int jl=g+j2, jh=g+j2+2;
      float2 a=v[jl];
      float2 wb=cmulf(v[jh], tw((j2*32+t)*2, -1.f));
      v[jl]=cadd(a,wb); v[jh]=csub(a,wb);
    }
  }
#pragma unroll
  for (int j=0;j<4;j++){
    float2 a=v[j];
    float2 wb=cmulf(v[j+4], tw(j*32+t, -1.f));
    v[j]=cadd(a,wb); v[j+4]=csub(a,wb);
  }
}

__device__ __forceinline__ float bredmax(float v, float* sh16){
#pragma unroll
  for (int m=16;m;m>>=1) v = fmaxf(v, __shfl_xor_sync(0xffffffffu, v, m));
  if (!(threadIdx.x&31)) sh16[threadIdx.x>>5]=v;
  __syncthreads();
  float r = sh16[0];
#pragma unroll
  for (int i=1;i<16;i++) r = fmaxf(r, sh16[i]);
  __syncthreads();
  return r;
}
__device__ __forceinline__ float bredsum(float v, float* sh16){
#pragma unroll
  for (int m=16;m;m>>=1) v += __shfl_xor_sync(0xffffffffu, v, m);
  if (!(threadIdx.x&31)) sh16[threadIdx.x>>5]=v;
  __syncthreads();
  float r = 0.f;
#pragma unroll
  for (int i=0;i<16;i++) r += sh16[i];
  __syncthreads();
  return r;
}

// ---------------- setup ----------------
__global__ void k_setup(){
  int t = threadIdx.x;
  if (t < HSc){
    double sf = 4.0*t + 1.5;
    int s0 = 4*t - 6;
    double w[16], ws=0.0;
    for (int j=0;j<16;j++){
      int i=s0+j;
      double kv = keysd(fabs(sf-(double)i)*0.25);
      if (i<0 || i>511) kv=0.0;
      w[j]=kv; ws+=kv;
    }
    for (int j=0;j<16;j++) g_wDT[j][t]=(float)(w[j]/ws);
    double sf2 = 0.5*t - 0.25;
    int b0 = (int)floor(sf2)-1;
    g_wU64s[t]=b0;
    double w4[4]; ws=0.0;
    for (int j=0;j<4;j++){
      int i=b0+j;
      double kv = keysd(fabs(sf2-(double)i));
      if (i<0||i>63) kv=0.0;
      w4[j]=kv; ws+=kv;
    }
    for (int j=0;j<4;j++) g_wU64T[j][t]=(float)(w4[j]/ws);
  }
  if (t < HMc){
    double sf = 0.25*t - 0.375;
    int b0 = (int)floor(sf)-1;
    g_wU128s[t]=b0;
    double w4[4], ws=0.0;
    for (int j=0;j<4;j++){
      int i=b0+j;
      double kv = keysd(fabs(sf-(double)i));
      if (i<0||i>127) kv=0.0;
      w4[j]=kv; ws+=kv;
    }
    for (int j=0;j<4;j++) g_wU128T[j][t]=(float)(w4[j]/ws);
  }
}

// ---------------- resize x-pass (raw) + BN row partials ----------------
__global__ void k_r1(const float* __restrict__ heat){
  int row = blockIdx.x;          // bl*512+y
  const float* src = heat + (size_t)row*HMc;
  int oc = threadIdx.x;
  const float4* s4 = (const float4*)src;
  float acc=0.f;
  float4 own;
  if (oc>=2 && oc<126){
    float x[20];
#pragma unroll
    for (int d=0; d<5; d++){
      float4 f = s4[oc-2+d];
      x[4*d]=f.x; x[4*d+1]=f.y; x[4*d+2]=f.z; x[4*d+3]=f.w;
    }
    own = make_float4(x[8],x[9],x[10],x[11]);
#pragma unroll
    for (int j=0;j<16;j++) acc = fmaf(g_wDT[j][oc], x[2+j], acc);
  } else {
    int s0 = 4*oc-6;
#pragma unroll
    for (int j=0;j<16;j++){
      int i = min(max(s0+j,0),HMc-1);
      acc = fmaf(g_wDT[j][oc], src[i], acc);
    }
    own = s4[oc];
  }
  g_tmpA[(size_t)row*HSc+oc] = acc;
  // BN partials: own covers src[4oc..4oc+3] exactly, disjoint across threads
  float s = own.x+own.y+own.z+own.w;
  float ss = fmaf(own.x,own.x, fmaf(own.y,own.y, fmaf(own.z,own.z, own.w*own.w)));
#pragma unroll
  for (int m=16;m;m>>=1){
    s  += __shfl_xor_sync(0xffffffffu, s, m);
    ss += __shfl_xor_sync(0xffffffffu, ss, m);
  }
  __shared__ float2 sw[4];
  if (!(oc&31)) sw[oc>>5]=make_float2(s,ss);
  __syncthreads();
  if (!oc){
    float2 a=sw[0],b=sw[1],c=sw[2],d=sw[3];
    g_rowbn[row]=make_float2(a.x+b.x+c.x+d.x, a.y+b.y+c.y+d.y);
  }
}
__global__ void k_bn_final(const float* __restrict__ gamma, const float* __restrict__ beta){
  int l = blockIdx.x, t = threadIdx.x;  // 256
  float s=0.f, ss=0.f;
  for (int i=t;i<1024;i+=256){
    int row = ((i<512)? l : (Lc+l))*HMc + (i&511);
    float2 v = g_rowbn[row];
    s+=v.x; ss+=v.y;
  }
  __shared__ float sh16[16];
#pragma unroll
  for (int m=16;m;m>>=1){ s += __shfl_xor_sync(0xffffffffu,s,m); ss += __shfl_xor_sync(0xffffffffu,ss,m); }
  __shared__ float2 sw[8];
  if (!(t&31)) sw[t>>5]=make_float2(s,ss);
  __syncthreads();
  if (!t){
    float S=0.f,SS=0.f;
#pragma unroll
    for (int i=0;i<8;i++){ S+=sw[i].x; SS+=sw[i].y; }
    const float N=524288.f;
    float mean=S/N, var=SS/N-mean*mean;
    float sc = gamma[l]*rsqrtf(var+1e-5f);
    g_scale[l]=sc;
    g_bofs[l]=beta[l]-mean*sc;
  }
  (void)sh16;
}

// y-pass (raw)
__global__ void k_r2(){
  int orow = blockIdx.x;         // bl*128+oy
  int bl = orow>>7, oy = orow&127;
  int oc = threadIdx.x;
  int s0 = 4*oy-6;
  float acc=0.f;
#pragma unroll
  for (int j=0;j<16;j++){
    int i = min(max(s0+j,0),HMc-1);
    acc = fmaf(g_wDT[j][oy], g_tmpA[((size_t)bl*HMc+i)*HSc+oc], acc);
  }
  g_hmrs[(size_t)orow*HSc+oc] = acc;
}

// ---------------- prior ----------------
__global__ void k_prior(const float* __restrict__ cond){
  int orow = blockIdx.x;
  int lk = orow>>7, oy = orow&127;
  int ox = threadIdx.x;
  int sy=g_wU64s[oy], sx=g_wU64s[ox];
  const float* src = cond + (size_t)lk*HCc*HCc;
  float wx[4];
#pragma unroll
  for (int j=0;j<4;j++) wx[j]=g_wU64T[j][ox];
  float acc=0.f;
#pragma unroll
  for (int a=0;a<4;a++){
    int iy = min(max(sy+a,0),HCc-1);
    float r=0.f;
#pragma unroll
    for (int b2=0;b2<4;b2++){
      int ix = min(max(sx+b2,0),HCc-1);
      r = fmaf(wx[b2], src[iy*HCc+ix], r);
    }
    acc = fmaf(g_wU64T[a][oy], r, acc);
  }
  g_prior[(size_t)orow*HSc+ox] = spb(acc);
}

// ---------------- merged row FFTs: blockIdx.y 0=prior, 1=like ----------------
__global__ void k_rows(const int* __restrict__ vidx, int lk0){
  int gw = lk0*HSc + blockIdx.x*8 + (threadIdx.x>>5);  // lk*128+row
  int t = threadIdx.x & 31;
  float2 v[8];
  if (blockIdx.y==0){
    const float* src = g_prior + (size_t)gw*HSc;
#pragma unroll
    for (int j=0;j<8;j++) v[j] = (j<4)? make_float2(src[j*32+t],0.f) : make_float2(0.f,0.f);
  } else {
    int lk = gw>>7, row = gw&127;
    int c = vidx[lk];
    float sc = g_scale[c], bo = g_bofs[c];
    const float* s0 = g_hmrs + (((size_t)c)*HSc+row)*HSc;
    const float* s1 = g_hmrs + (((size_t)(Lc+c))*HSc+row)*HSc;
#pragma unroll
    for (int j=0;j<8;j++){
      if (j<4){
        int x=j*32+t;
        v[j]=make_float2(spb(fmaf(s0[x],sc,bo)), spb(fmaf(s1[x],sc,bo)));
      } else v[j]=make_float2(0.f,0.f);
    }
  }
  fft_fwd(v,t);
  float2* dst = (blockIdx.y==0 ? g_RP : g_RL) + (size_t)gw*NFFT;
#pragma unroll
  for (int j=0;j<8;j++) dst[j*32+t]=v[j];
}

// ---------------- columns: likeFFT x priorFFT -> inverse ----------------
__global__ void k_cols_conv(int lk0){
  __shared__ float2 tl[128][9];
  __shared__ float2 tp[128][9];
  int kx0 = blockIdx.x*8;
  int lk = lk0 + blockIdx.y;
  int tid = threadIdx.x;
  const float2* srcL = g_RL + (size_t)lk*HSc*NFFT;
  const float2* srcP = g_RP + (size_t)lk*HSc*NFFT;
  for (int i=tid;i<1024;i+=256){
    int r=i>>3, c=i&7;
    tl[r][c]=__ldcs(&srcL[r*NFFT + kx0 + c]);
    tp[r][c]=__ldcs(&srcP[r*NFFT + kx0 + c]);
  }
  __syncthreads();
  int w = tid>>5, t = tid&31;
  float2 vp[8], v[8];
#pragma unroll
  for (int j=0;j<8;j++){
    vp[j] = (j<4)? tp[j*32+t][w] : make_float2(0.f,0.f);
    v[j]  = (j<4)? tl[j*32+t][w] : make_float2(0.f,0.f);
  }
  fft_fwd(vp,t);
  fft_fwd(v,t);
#pragma unroll
  for (int j=0;j<8;j++) v[j]=cmulf(v[j], vp[j]);
  fft_inv(v,t);
#pragma unroll
  for (int j=2;j<6;j++) tl[(j-2)*32+t][w]=v[j];
  __syncthreads();
  float2* dst = g_TL + (size_t)lk*HSc*NFFT;
  for (int i=tid;i<1024;i+=256){
    int r=i>>3, c=i&7;
    dst[r*NFFT + kx0 + c]=tl[r][c];
  }
}

// ---------------- inverse row FFT + log-energy over K ----------------
__global__ void k_energy(const float* __restrict__ bias, int l0){
  __shared__ float sm0[8][128], sm1[8][128];
  int ly = blockIdx.x;             // (l-l0)*128+y
  int y = ly&127, l = l0 + (ly>>7);
  int tid = threadIdx.x;
  int k = tid>>5, t = tid&31;
  int lk = l*Kc + k;
  const float2* src = g_TL + ((size_t)lk*HSc + y)*NFFT;
  float2 v[8];
#pragma unroll
  for (int j=0;j<8;j++) v[j]=__ldcs(&src[j*32+t]);
  fft_inv(v,t);
  const float sc = 1.f/65536.f;
  const float* bi = bias + ((size_t)lk*HSc + y)*HSc;
#pragma unroll
  for (int j=2;j<6;j++){
    int x = (j-2)*32 + t;
    float sb = spb(bi[x]);
    sm0[k][x] = logf(fmaf(v[j].x, sc, sb) + 1e-6f);
    sm1[k][x] = logf(fmaf(v[j].y, sc, sb) + 1e-6f);
  }
  __syncthreads();
  if (tid < 128){
    float e=0.f;
#pragma unroll
    for (int kk=0;kk<8;kk++) e += sm0[kk][tid];
    g_energy128[(((size_t)l)*HSc+y)*HSc+tid]=e;
  } else {
    int x = tid-128;
    float e=0.f;
#pragma unroll
    for (int kk=0;kk<8;kk++) e += sm1[kk][x];
    g_energy128[(((size_t)(Lc+l))*HSc+y)*HSc+x]=e;
  }
}

// ---------------- upsample 128->512 ----------------
__global__ void k_u1(){
  int r = blockIdx.x;              // bl*128+y
  int X = threadIdx.x;
  int s0 = g_wU128s[X];
  const float* src = g_energy128 + (size_t)r*HSc;
  float acc=0.f;
#pragma unroll
  for (int j=0;j<4;j++){
    int i = min(max(s0+j,0),HSc-1);
    acc = fmaf(g_wU128T[j][X], src[i], acc);
  }
  g_tmpA[(size_t)r*HMc+X]=acc;
}
__global__ void k_u2(const float* __restrict__ heat){
  int rY = blockIdx.x;             // bl*512+Y
  int bl = rY>>9, Y = rY&511;
  int l = bl % Lc;
  int X = threadIdx.x;
  int s0 = g_wU128s[Y];
  float acc=0.f;
#pragma unroll
  for (int j=0;j<4;j++){
    int i = min(max(s0+j,0),HSc-1);
    acc = fmaf(g_wU128T[j][Y], g_tmpA[((size_t)bl*HSc+i)*HMc+X], acc);
  }
  float h = heat[(size_t)rY*HMc+X];
  float hm = fmaf(h, g_scale[l], g_bofs[l]);
  float e = acc + logf(spb(hm)+1e-6f);
  __shared__ float sh16[16];
  float m = bredmax(e, sh16);
  float p = __expf(e - m);
  float s = bredsum(p, sh16);
  float sx = bredsum(p*(float)X, sh16);
  if (!X) g_rs[rY]=make_float4(m, s, sx, 0.f);
}
__global__ void k_final(float* __restrict__ out){
  int bl=blockIdx.x, t=threadIdx.x;
  float4 v = g_rs[bl*HMc+t];
  __shared__ float sh16[16];
  float gmax = bredmax(v.x, sh16);
  float w = __expf(v.x - gmax);
  float s0 = bredsum(v.y*w, sh16);
  float s1 = bredsum(v.z*w, sh16);
  float s2 = bredsum((float)t*v.y*w, sh16);
  if (!t){
    out[bl*3+0]=1.f;
    out[bl*3+1]=s2/s0;
    out[bl*3+2]=s1/s0;
  }
}

extern "C" void kernel_launch(void* const* d_in, const int* in_sizes, int n_in,
                              void* d_out, int out_size){
  const float* heat  = (const float*)d_in[0];
  const float* cond  = (const float*)d_in[1];
  const float* bias  = (const float*)d_in[2];
  const float* gamma = (const float*)d_in[3];
  const float* beta  = (const float*)d_in[4];
  const int*   vidx  = (const int*)d_in[5];
  float* out = (float*)d_out;

  k_setup<<<1,512>>>();
  k_r1<<<NBL*HMc,128>>>(heat);
  k_bn_final<<<Lc,256>>>(gamma, beta);
  k_r2<<<NBL*HSc,128>>>();
  k_prior<<<NIMGP*HSc,128>>>(cond);
  // chunk 0: lk [0,144), l [0,18)
  k_rows<<<dim3(LKSPLIT*HSc/8,2),256>>>(vidx, 0);
  k_cols_conv<<<dim3(32,LKSPLIT),256>>>(0);
  k_energy<<<LSPLIT*HSc,256>>>(bias, 0);
  // chunk 1: lk [144,296), l [18,37)
  k_rows<<<dim3((NIMGP-LKSPLIT)*HSc/8,2),256>>>(vidx, LKSPLIT);
  k_cols_conv<<<dim3(32,NIMGP-LKSPLIT),256>>>(LKSPLIT);
  k_energy<<<(Lc-LSPLIT)*HSc,256>>>(bias, LSPLIT);
  k_u1<<<NBL*HSc,512>>>();
  k_u2<<<NBL*HMc,512>>>(heat);
  k_final<<<NBL,512>>>(out);
}